// round 16
// baseline (speedup 1.0000x reference)
#include <cuda_runtime.h>
#include <cuda_bf16.h>
#include <cstdint>

// Problem constants
#define B_  64
#define S_  2048
#define E_  256
#define H_  256
#define M_TOT (B_ * S_)        // 131072 rows

// Scratch (device-global: runtime allocation is forbidden)
__device__ float         g_xw [(size_t)M_TOT * H_];   // 128 MB
__device__ __nv_bfloat16 g_Whi[H_ * E_];
__device__ __nv_bfloat16 g_Wlo[H_ * E_];
__device__ float         g_UwT[H_ * H_];              // UwT[k][h] = Uw[h][k]

// Fast tanh: 1 - 2/(e^{2x}+1). |err| ~1e-6; exact saturation at +/-inf.
__device__ __forceinline__ float fast_tanh(float x) {
    float e = __expf(2.0f * x);
    float r;
    asm("rcp.approx.f32 %0, %1;" : "=f"(r) : "f"(e + 1.0f));
    return fmaf(-2.0f, r, 1.0f);
}

// ---------------------------------------------------------------------------
// prep (merged): UwT transpose + Ww hi/lo split
// ---------------------------------------------------------------------------
__global__ void prep(const float* __restrict__ Uw, const float* __restrict__ Ww) {
    int k = blockIdx.x, h = threadIdx.x;
    g_UwT[k * H_ + h] = Uw[h * H_ + k];
    int i = k * H_ + h;                 // covers H*E = 65536
    float v = Ww[i];
    __nv_bfloat16 hb = __float2bfloat16_rn(v);
    g_Whi[i] = hb;
    g_Wlo[i] = __float2bfloat16_rn(v - __bfloat162float(hb));
}

// ---------------------------------------------------------------------------
// Fused split-bf16 tensor-core GEMM, occupancy-tuned:
//   xw = x_hi*W_hi + x_lo*W_hi + x_hi*W_lo + Wb
//   CTA tile 128(M) x 64(N), 8 warps = 4(M) x 2(N), warp tile 32 x 32.
//   acc 32 regs -> 3 CTAs/SM (launch_bounds).
//   A: fp32 load -> in-register split -> STS (reg-prefetched).
//   B: cp.async into double-buffered stage; issued right after the first
//      barrier so the whole compute phase covers its latency.
// ---------------------------------------------------------------------------
#define ASTR 40
#define CTM 128
#define CTN 64

__device__ __forceinline__ void ldmx4(uint32_t& r0, uint32_t& r1, uint32_t& r2, uint32_t& r3,
                                      uint32_t addr) {
    asm volatile("ldmatrix.sync.aligned.m8n8.x4.shared.b16 {%0,%1,%2,%3}, [%4];"
                 : "=r"(r0), "=r"(r1), "=r"(r2), "=r"(r3) : "r"(addr));
}
__device__ __forceinline__ void mma16816(float* d, const uint32_t* a,
                                         uint32_t b0, uint32_t b1) {
    asm volatile("mma.sync.aligned.m16n8k16.row.col.f32.bf16.bf16.f32 "
                 "{%0,%1,%2,%3}, {%4,%5,%6,%7}, {%8,%9}, {%0,%1,%2,%3};"
                 : "+f"(d[0]), "+f"(d[1]), "+f"(d[2]), "+f"(d[3])
                 : "r"(a[0]), "r"(a[1]), "r"(a[2]), "r"(a[3]), "r"(b0), "r"(b1));
}
__device__ __forceinline__ void cpasync16(uint32_t smem, const void* g) {
    asm volatile("cp.async.cg.shared.global [%0], [%1], 16;"
                 :: "r"(smem), "l"(g) : "memory");
}

__device__ __forceinline__ void split4(float4 v, uint32_t* hi, uint32_t* lo) {
    __nv_bfloat16 h0 = __float2bfloat16_rn(v.x);
    __nv_bfloat16 h1 = __float2bfloat16_rn(v.y);
    __nv_bfloat16 h2 = __float2bfloat16_rn(v.z);
    __nv_bfloat16 h3 = __float2bfloat16_rn(v.w);
    __nv_bfloat162 H0(h0, h1), H1(h2, h3);
    __nv_bfloat162 L0(__float2bfloat16_rn(v.x - __bfloat162float(h0)),
                      __float2bfloat16_rn(v.y - __bfloat162float(h1)));
    __nv_bfloat162 L1(__float2bfloat16_rn(v.z - __bfloat162float(h2)),
                      __float2bfloat16_rn(v.w - __bfloat162float(h3)));
    hi[0] = *(uint32_t*)&H0; hi[1] = *(uint32_t*)&H1;
    lo[0] = *(uint32_t*)&L0; lo[1] = *(uint32_t*)&L1;
}

__global__ __launch_bounds__(256, 3) void gemm_fused(const float* __restrict__ x,
                                                     const float* __restrict__ Wb) {
    __shared__ __nv_bfloat16 Ahi[CTM * ASTR];              // 10 KB
    __shared__ __nv_bfloat16 Alo[CTM * ASTR];              // 10 KB
    __shared__ __nv_bfloat16 Bhi2[2][CTN * ASTR];          // 2 x 5 KB
    __shared__ __nv_bfloat16 Blo2[2][CTN * ASTR];          // 2 x 5 KB

    const int tid   = threadIdx.x;
    const int lane  = tid & 31;
    const int warp  = tid >> 5;
    const int warpM = warp >> 1;           // 0..3, 32 rows
    const int warpN = warp & 1;            // 0..1, 32 cols
    const int grp   = lane >> 2;
    const int qid   = lane & 3;

    const size_t row0 = (size_t)blockIdx.y * CTM;
    const int    n0   = blockIdx.x * CTN;

    const int arow = tid >> 1, ahalf = (tid & 1) * 16;     // A: 128 rows x 32 k
    const int brow = tid >> 1, bhalf = (tid & 1) * 16;     // B: 64 rows (tid<128)

    float d[2][4][4];
    #pragma unroll
    for (int i = 0; i < 2; i++)
        #pragma unroll
        for (int j = 0; j < 4; j++)
            #pragma unroll
            for (int c = 0; c < 4; c++) d[i][j][c] = 0.0f;

    uint32_t ah_base = (uint32_t)__cvta_generic_to_shared(Ahi);
    uint32_t al_base = (uint32_t)__cvta_generic_to_shared(Alo);
    uint32_t bh_base[2] = { (uint32_t)__cvta_generic_to_shared(Bhi2[0]),
                            (uint32_t)__cvta_generic_to_shared(Bhi2[1]) };
    uint32_t bl_base[2] = { (uint32_t)__cvta_generic_to_shared(Blo2[0]),
                            (uint32_t)__cvta_generic_to_shared(Blo2[1]) };

    const float* xrow = x + (row0 + arow) * E_ + ahalf;
    const __nv_bfloat16* whrow = g_Whi + (size_t)(n0 + brow) * E_ + bhalf;
    const __nv_bfloat16* wlrow = g_Wlo + (size_t)(n0 + brow) * E_ + bhalf;
    const uint32_t bsoff = (uint32_t)(brow * ASTR + bhalf) * 2;   // B smem byte off

    // Prologue: A(0) regs; cp.async B(0) -> stage 0
    float4 fa0 = *(const float4*)&xrow[0];
    float4 fa1 = *(const float4*)&xrow[4];
    float4 fa2 = *(const float4*)&xrow[8];
    float4 fa3 = *(const float4*)&xrow[12];
    if (tid < 128) {
        cpasync16(bh_base[0] + bsoff +  0, whrow + 0);
        cpasync16(bh_base[0] + bsoff + 16, whrow + 8);
        cpasync16(bl_base[0] + bsoff +  0, wlrow + 0);
        cpasync16(bl_base[0] + bsoff + 16, wlrow + 8);
    }
    asm volatile("cp.async.commit_group;" ::: "memory");

    for (int kc = 0; kc < 8; kc++) {
        const int cb = kc & 1;

        // STS A(kc) from regs (split in-register)
        {
            uint32_t h[8], l[8];
            split4(fa0, h + 0, l + 0);
            split4(fa1, h + 2, l + 2);
            split4(fa2, h + 4, l + 4);
            split4(fa3, h + 6, l + 6);
            *(uint4*)&Ahi[arow * ASTR + ahalf + 0] = make_uint4(h[0], h[1], h[2], h[3]);
            *(uint4*)&Ahi[arow * ASTR + ahalf + 8] = make_uint4(h[4], h[5], h[6], h[7]);
            *(uint4*)&Alo[arow * ASTR + ahalf + 0] = make_uint4(l[0], l[1], l[2], l[3]);
            *(uint4*)&Alo[arow * ASTR + ahalf + 8] = make_uint4(l[4], l[5], l[6], l[7]);
        }
        // Prefetch A(kc+1) into regs (covered by wait+sync+compute)
        if (kc + 1 < 8) {
            const int ko = (kc + 1) * 32;
            fa0 = *(const float4*)&xrow[ko + 0];
            fa1 = *(const float4*)&xrow[ko + 4];
            fa2 = *(const float4*)&xrow[ko + 8];
            fa3 = *(const float4*)&xrow[ko + 12];
        }

        asm volatile("cp.async.wait_group 0;" ::: "memory");   // B(kc) arrived
        __syncthreads();                                       // A(kc)+B(kc) visible

        // Issue B(kc+1) into the other stage; compute below covers its latency
        if (kc + 1 < 8) {
            const int ko = (kc + 1) * 32;
            if (tid < 128) {
                cpasync16(bh_base[cb ^ 1] + bsoff +  0, whrow + ko + 0);
                cpasync16(bh_base[cb ^ 1] + bsoff + 16, whrow + ko + 8);
                cpasync16(bl_base[cb ^ 1] + bsoff +  0, wlrow + ko + 0);
                cpasync16(bl_base[cb ^ 1] + bsoff + 16, wlrow + ko + 8);
            }
            asm volatile("cp.async.commit_group;" ::: "memory");
        }

        // Compute: 2 k16 slices, 3 split products each
        #pragma unroll
        for (int k16 = 0; k16 < 32; k16 += 16) {
            uint32_t ahi[2][4], alo[2][4];
            #pragma unroll
            for (int i = 0; i < 2; i++) {
                int r = warpM * 32 + i * 16 + (lane & 15);
                int c = k16 + ((lane >> 4) << 3);
                uint32_t off = (uint32_t)(r * ASTR + c) * 2;
                ldmx4(ahi[i][0], ahi[i][1], ahi[i][2], ahi[i][3], ah_base + off);
                ldmx4(alo[i][0], alo[i][1], alo[i][2], alo[i][3], al_base + off);
            }
            #pragma unroll
            for (int j2 = 0; j2 < 2; j2++) {
                int n = warpN * 32 + j2 * 16 + (((lane >> 4) & 1) << 3) + (lane & 7);
                int c = k16 + (((lane >> 3) & 1) << 3);
                uint32_t off = (uint32_t)(n * ASTR + c) * 2;
                uint32_t bh[4], bl[4];
                ldmx4(bh[0], bh[1], bh[2], bh[3], bh_base[cb] + off);
                ldmx4(bl[0], bl[1], bl[2], bl[3], bl_base[cb] + off);
                #pragma unroll
                for (int i = 0; i < 2; i++)
                    #pragma unroll
                    for (int sel = 0; sel < 2; sel++) {
                        float* dd = d[i][j2 * 2 + sel];
                        mma16816(dd, ahi[i], bh[sel * 2], bh[sel * 2 + 1]);  // hi*hi
                        mma16816(dd, alo[i], bh[sel * 2], bh[sel * 2 + 1]);  // lo*hi
                        mma16816(dd, ahi[i], bl[sel * 2], bl[sel * 2 + 1]);  // hi*lo
                    }
            }
        }
        __syncthreads();                                       // A smem free
    }

    // epilogue: add bias, store fp32
    #pragma unroll
    for (int j = 0; j < 4; j++) {
        int col = n0 + warpN * 32 + j * 8 + qid * 2;
        float2 wb = *(const float2*)&Wb[col];
        #pragma unroll
        for (int i = 0; i < 2; i++) {
            size_t r = row0 + warpM * 32 + i * 16 + grp;
            float2 o0 = make_float2(d[i][j][0] + wb.x, d[i][j][1] + wb.y);
            float2 o1 = make_float2(d[i][j][2] + wb.x, d[i][j][3] + wb.y);
            *(float2*)&g_xw[r * H_ + col]       = o0;
            *(float2*)&g_xw[(r + 8) * H_ + col] = o1;
        }
    }
}

// ---------------------------------------------------------------------------
// Scan: one CTA per batch, 256 threads. The proven R6/R13 loop — UNCHANGED.
// ---------------------------------------------------------------------------
#define UREG 192
#define USM  (H_ - UREG)

#define SCAN_SMEM_FLOATS (USM * H_ + 2 * H_)
#define SMEM_BYTES (SCAN_SMEM_FLOATS * 4)

__global__ __launch_bounds__(256, 1)
void rnn_scan(const float* __restrict__ Ub,
              float* __restrict__ Out,     // [B,S,H]
              float* __restrict__ Tfin) {  // [B,H]
    extern __shared__ float sm[];
    float2* u2  = (float2*)sm;
    float*  vsm = sm + (size_t)USM * H_;

    const int tid = threadIdx.x;
    const int b   = blockIdx.x;

    float uw[UREG];
    #pragma unroll
    for (int j = 0; j < UREG; j++)
        uw[j] = g_UwT[j * H_ + tid];

    for (int r2 = 0; r2 < USM / 2; r2++) {
        float a = g_UwT[(UREG + 2 * r2 + 0) * H_ + tid];
        float c = g_UwT[(UREG + 2 * r2 + 1) * H_ + tid];
        u2[r2 * H_ + tid] = make_float2(a, c);
    }
    __syncthreads();

    const float ub = Ub[tid];
    float t = 0.0f;

    const float* xwp = g_xw + (size_t)b * S_ * H_ + tid;
    float*       op  = Out  + (size_t)b * S_ * H_ + tid;

    float xv = __ldcs(xwp);

    for (int s = 0; s < S_; s++) {
        float v = fast_tanh(xv + t);
        float* vb = vsm + (s & 1) * H_;
        vb[tid] = v;
        __syncthreads();

        if (s + 1 < S_) xv = __ldcs(xwp + (size_t)(s + 1) * H_);

        const float4* v4 = (const float4*)vb;
        float a0 = ub, a1 = 0.f, a2 = 0.f, a3 = 0.f;
        float a4 = 0.f, a5 = 0.f, a6 = 0.f, a7 = 0.f;

        float4 vA = v4[0];
        float4 vB = v4[1];

        #pragma unroll
        for (int q = 0; q < 48; q += 2) {
            float4 nA = v4[q + 2];
            float4 nB = v4[q + 3];
            const int j = 4 * q;
            a0 += uw[j + 0] * vA.x;  a1 += uw[j + 1] * vA.y;
            a2 += uw[j + 2] * vA.z;  a3 += uw[j + 3] * vA.w;
            a4 += uw[j + 4] * vB.x;  a5 += uw[j + 5] * vB.y;
            a6 += uw[j + 6] * vB.z;  a7 += uw[j + 7] * vB.w;
            vA = nA; vB = nB;
        }

        const float2* up = u2 + tid;
        #pragma unroll
        for (int q = 48; q < 64; q += 2) {
            float4 nA, nB;
            if (q + 2 < 64) { nA = v4[q + 2]; nB = v4[q + 3]; }
            else            { nA = vA;        nB = vB;        }
            const int r2b = (4 * q - UREG) >> 1;
            float2 u0 = up[(r2b + 0) * H_];
            float2 u1 = up[(r2b + 1) * H_];
            float2 uu = up[(r2b + 2) * H_];
            float2 u3 = up[(r2b + 3) * H_];
            a0 += u0.x * vA.x;  a1 += u0.y * vA.y;
            a2 += u1.x * vA.z;  a3 += u1.y * vA.w;
            a4 += uu.x * vB.x;  a5 += uu.y * vB.y;
            a6 += u3.x * vB.z;  a7 += u3.y * vB.w;
            vA = nA; vB = nB;
        }

        t = ((a0 + a1) + (a2 + a3)) + ((a4 + a5) + (a6 + a7));
        __stcs(&op[(size_t)s * H_], t);
    }

    Tfin[b * H_ + tid] = t;
}

// ---------------------------------------------------------------------------
// Launcher (serial: merged prep -> occupancy-tuned GEMM -> solo scan)
// ---------------------------------------------------------------------------
extern "C" void kernel_launch(void* const* d_in, const int* in_sizes, int n_in,
                              void* d_out, int out_size) {
    const float* x  = (const float*)d_in[0];   // [B,S,E]
    const float* Ww = (const float*)d_in[1];   // [H,E]
    const float* Wb = (const float*)d_in[2];   // [H]
    const float* Uw = (const float*)d_in[3];   // [H,H]
    const float* Ub = (const float*)d_in[4];   // [H]

    float* out  = (float*)d_out;
    float* tfin = out;                          // [B,H]
    float* O    = out + (size_t)B_ * H_;        // [B,S,H]

    cudaFuncSetAttribute(rnn_scan, cudaFuncAttributeMaxDynamicSharedMemorySize,
                         SMEM_BYTES);

    prep<<<H_, H_>>>(Uw, Ww);
    gemm_fused<<<dim3(H_ / CTN, M_TOT / CTM), 256>>>(x, Wb);
    rnn_scan<<<B_, 256, SMEM_BYTES>>>(Ub, O, tfin);
}